// round 6
// baseline (speedup 1.0000x reference)
#include <cuda_runtime.h>
#include <cuda_bf16.h>
#include <math.h>
#include <cstdint>

#define B_     16
#define L_     784
#define D_     384
#define H_     8
#define QK_    32
#define VD_    128
#define EH_    192          // per-head qkv width
#define QKVN_  1536
#define RESI_  625

#define FQT 112             // q rows per CTA (784 = 7*112)
#define FCK 112             // keys per chunk
#define VSTR 136            // V smem stride in bf16 (conflict-free trans ldsm)
#define KSTR 40             // K/Q smem stride in bf16
#define AON  (H_ * VD_)     // 1024

// ---------------- scratch (static device globals; no runtime alloc) --------
__device__ __nv_bfloat16 g_qkvh[(size_t)B_ * L_ * QKVN_];   // 38.6 MB
__device__ __nv_bfloat16 g_qkvl[(size_t)B_ * L_ * QKVN_];   // 38.6 MB
__device__ __nv_bfloat16 g_aoh[(size_t)B_ * L_ * AON];      // 25.7 MB
__device__ __nv_bfloat16 g_aol[(size_t)B_ * L_ * AON];      // 25.7 MB
__device__ __nv_bfloat16 g_biasbf[(size_t)H_ * L_ * L_];    // 9.8 MB
__device__ float g_abg[(size_t)H_ * RESI_ * RESI_];         // 12.5 MB
__device__ __nv_bfloat16 g_xh[(size_t)B_ * L_ * D_];
__device__ __nv_bfloat16 g_xl[(size_t)B_ * L_ * D_];
__device__ __nv_bfloat16 g_wqh[QKVN_ * D_];
__device__ __nv_bfloat16 g_wql[QKVN_ * D_];
__device__ __nv_bfloat16 g_wph[D_ * AON];
__device__ __nv_bfloat16 g_wpl[D_ * AON];
__device__ float g_iw[L_ * 4];
__device__ int   g_ii[L_ * 4];

__device__ __forceinline__ uint32_t smem_u32(const void* p) {
    uint32_t a;
    asm("{ .reg .u64 t; cvta.to.shared.u64 t, %1; cvt.u32.u64 %0, t; }" : "=r"(a) : "l"(p));
    return a;
}
__device__ __forceinline__ uint32_t pkbf(float a, float b) {
    __nv_bfloat162 t = __floats2bfloat162_rn(a, b);
    return *reinterpret_cast<uint32_t*>(&t);
}

// ---------------- K0: bicubic interp weights/indices -----------------------
__global__ void build_interp_kernel() {
    int o = blockIdx.x * blockDim.x + threadIdx.x;
    if (o >= L_) return;
    const float a = -0.75f;
    float scale = (float)RESI_ / (float)L_;
    float src = ((float)o + 0.5f) * scale - 0.5f;
    float f = floorf(src);
    float t = src - f;
    float xs[4] = { t + 1.0f, t, 1.0f - t, 2.0f - t };
#pragma unroll
    for (int i = 0; i < 4; i++) {
        float ax = fabsf(xs[i]);
        float w1 = ((a + 2.0f) * ax - (a + 3.0f)) * ax * ax + 1.0f;
        float w2 = a * (((ax - 5.0f) * ax + 8.0f) * ax - 4.0f);
        float w = (ax <= 1.0f) ? w1 : ((ax < 2.0f) ? w2 : 0.0f);
        g_iw[o * 4 + i] = w;
        int id = (int)f - 1 + i;
        id = id < 0 ? 0 : (id > RESI_ - 1 ? RESI_ - 1 : id);
        g_ii[o * 4 + i] = id;
    }
}

// ---------------- K1: ab gather --------------------------------------------
__global__ void gather_ab_kernel(const float* __restrict__ ab_table,
                                 const int* __restrict__ bias_idxs) {
    int i = blockIdx.x * blockDim.x + threadIdx.x;
    const int total = H_ * RESI_ * RESI_;
    if (i >= total) return;
    int h = i / (RESI_ * RESI_);
    int ij = i - h * (RESI_ * RESI_);
    g_abg[i] = ab_table[h * RESI_ + bias_idxs[ij]];
}

// ---------------- K2: bias build (bf16 out) --------------------------------
__global__ void build_bias_kernel() {
    int i = blockIdx.x * blockDim.x + threadIdx.x;
    const int total = H_ * L_ * L_;
    if (i >= total) return;
    int h = i / (L_ * L_);
    int r = i - h * (L_ * L_);
    int o = r / L_;
    int p = r - o * L_;
    const float* __restrict__ abh = g_abg + (size_t)h * RESI_ * RESI_;
    float wp[4]; int ip[4];
#pragma unroll
    for (int bb = 0; bb < 4; bb++) { wp[bb] = g_iw[p * 4 + bb]; ip[bb] = g_ii[p * 4 + bb]; }
    float s = 0.f;
#pragma unroll
    for (int aa = 0; aa < 4; aa++) {
        float wa = g_iw[o * 4 + aa];
        const float* row = abh + (size_t)g_ii[o * 4 + aa] * RESI_;
        float sb = 0.f;
#pragma unroll
        for (int bb = 0; bb < 4; bb++) sb = fmaf(wp[bb], __ldg(row + ip[bb]), sb);
        s = fmaf(wa, sb, s);
    }
    g_biasbf[i] = __float2bfloat16(s);
}

// ---------------- split kernel: f32 -> bf16 hi + lo ------------------------
__global__ void split_kernel(const float* __restrict__ src,
                             __nv_bfloat16* __restrict__ dh,
                             __nv_bfloat16* __restrict__ dl, int n4) {
    int i = blockIdx.x * blockDim.x + threadIdx.x;
    if (i >= n4) return;
    float4 v = *(const float4*)(src + (size_t)i * 4);
    __nv_bfloat162 h01 = __floats2bfloat162_rn(v.x, v.y);
    __nv_bfloat162 h23 = __floats2bfloat162_rn(v.z, v.w);
    float l0 = v.x - __bfloat162float(h01.x), l1 = v.y - __bfloat162float(h01.y);
    float l2 = v.z - __bfloat162float(h23.x), l3 = v.w - __bfloat162float(h23.y);
    *(uint2*)(dh + (size_t)i * 4) = make_uint2(*(uint32_t*)&h01, *(uint32_t*)&h23);
    *(uint2*)(dl + (size_t)i * 4) = make_uint2(pkbf(l0, l1), pkbf(l2, l3));
}

// ---------------- mma.sync helpers -----------------------------------------
__device__ __forceinline__ void ldsm4(uint32_t& r0, uint32_t& r1, uint32_t& r2, uint32_t& r3,
                                      uint32_t addr) {
    asm volatile("ldmatrix.sync.aligned.m8n8.x4.shared.b16 {%0,%1,%2,%3}, [%4];"
                 : "=r"(r0), "=r"(r1), "=r"(r2), "=r"(r3) : "r"(addr));
}
__device__ __forceinline__ void ldsm2(uint32_t& r0, uint32_t& r1, uint32_t addr) {
    asm volatile("ldmatrix.sync.aligned.m8n8.x2.shared.b16 {%0,%1}, [%2];"
                 : "=r"(r0), "=r"(r1) : "r"(addr));
}
__device__ __forceinline__ void ldsm2t(uint32_t& r0, uint32_t& r1, uint32_t addr) {
    asm volatile("ldmatrix.sync.aligned.m8n8.x2.trans.shared.b16 {%0,%1}, [%2];"
                 : "=r"(r0), "=r"(r1) : "r"(addr));
}
__device__ __forceinline__ void mma16816(float* d, const uint32_t* a, const uint32_t* b) {
    asm volatile("mma.sync.aligned.m16n8k16.row.col.f32.bf16.bf16.f32 "
                 "{%0,%1,%2,%3}, {%4,%5,%6,%7}, {%8,%9}, {%0,%1,%2,%3};"
                 : "+f"(d[0]), "+f"(d[1]), "+f"(d[2]), "+f"(d[3])
                 : "r"(a[0]), "r"(a[1]), "r"(a[2]), "r"(a[3]), "r"(b[0]), "r"(b[1]));
}

// ---------------- K3/K5: bf16-split GEMM on pre-split inputs ----------------
// MODE 0: epilogue writes split bf16 (Ch, Cl).  MODE 1: writes f32 + bias.
#define GS 40
template <int MODE>
__global__ __launch_bounds__(256) void mma_gemm_nt(
    const __nv_bfloat16* __restrict__ Ahg, const __nv_bfloat16* __restrict__ Alg,
    const __nv_bfloat16* __restrict__ Whg, const __nv_bfloat16* __restrict__ Wlg,
    const float* __restrict__ bias,
    __nv_bfloat16* __restrict__ Ch, __nv_bfloat16* __restrict__ Cl,
    float* __restrict__ Cf,
    int M, int N, int K)
{
    __shared__ __align__(16) __nv_bfloat16 Ah[128][GS];
    __shared__ __align__(16) __nv_bfloat16 Al[128][GS];
    __shared__ __align__(16) __nv_bfloat16 Bh[128][GS];
    __shared__ __align__(16) __nv_bfloat16 Bl[128][GS];

    const int tid = threadIdx.x;
    const int wid = tid >> 5;
    const int lane = tid & 31;
    const int wm = wid >> 2;
    const int wn = wid & 3;
    const int bm = blockIdx.y * 128;
    const int bn = blockIdx.x * 128;

    float acc[4][4][4];
#pragma unroll
    for (int i = 0; i < 4; i++)
#pragma unroll
        for (int j = 0; j < 4; j++)
#pragma unroll
            for (int e = 0; e < 4; e++) acc[i][j][e] = 0.f;

    const int q = lane >> 3;
    const int rr = lane & 7;

    for (int k0 = 0; k0 < K; k0 += 32) {
        // stage tiles: each thread moves 2 uint4 per matrix (128x32 bf16)
#pragma unroll
        for (int it = 0; it < 2; it++) {
            int idx = tid + it * 256;      // 0..511
            int row = idx >> 2;
            int c8 = (idx & 3) << 3;       // 0,8,16,24
            *(uint4*)&Ah[row][c8] = *(const uint4*)(Ahg + (size_t)(bm + row) * K + k0 + c8);
            *(uint4*)&Al[row][c8] = *(const uint4*)(Alg + (size_t)(bm + row) * K + k0 + c8);
            *(uint4*)&Bh[row][c8] = *(const uint4*)(Whg + (size_t)(bn + row) * K + k0 + c8);
            *(uint4*)&Bl[row][c8] = *(const uint4*)(Wlg + (size_t)(bn + row) * K + k0 + c8);
        }
        __syncthreads();

#pragma unroll
        for (int ks = 0; ks < 2; ks++) {
            int kc = ks * 16;
            uint32_t ah[4][4], al[4][4];
#pragma unroll
            for (int i = 0; i < 4; i++) {
                int arow = wm * 64 + i * 16 + (q & 1) * 8 + rr;
                int acol = kc + (q >> 1) * 8;
                ldsm4(ah[i][0], ah[i][1], ah[i][2], ah[i][3], smem_u32(&Ah[arow][acol]));
                ldsm4(al[i][0], al[i][1], al[i][2], al[i][3], smem_u32(&Al[arow][acol]));
            }
            uint32_t bh[4][2], bl[4][2];
#pragma unroll
            for (int j = 0; j < 4; j++) {
                int brow = wn * 32 + j * 8 + rr;
                int bcol = kc + (q & 1) * 8;
                ldsm2(bh[j][0], bh[j][1], smem_u32(&Bh[brow][bcol]));
                ldsm2(bl[j][0], bl[j][1], smem_u32(&Bl[brow][bcol]));
            }
#pragma unroll
            for (int i = 0; i < 4; i++)
#pragma unroll
                for (int j = 0; j < 4; j++) {
                    mma16816(acc[i][j], ah[i], bh[j]);
                    mma16816(acc[i][j], ah[i], bl[j]);
                    mma16816(acc[i][j], al[i], bh[j]);
                }
        }
        __syncthreads();
    }

    const int gid = lane >> 2;
    const int tig = lane & 3;
#pragma unroll
    for (int i = 0; i < 4; i++) {
#pragma unroll
        for (int j = 0; j < 4; j++) {
            int row0 = bm + wm * 64 + i * 16 + gid;
            int col = bn + wn * 32 + j * 8 + tig * 2;
            if (MODE == 1) {
                float2 v0 = make_float2(acc[i][j][0] + bias[col], acc[i][j][1] + bias[col + 1]);
                float2 v1 = make_float2(acc[i][j][2] + bias[col], acc[i][j][3] + bias[col + 1]);
                *(float2*)(Cf + (size_t)row0 * N + col) = v0;
                *(float2*)(Cf + (size_t)(row0 + 8) * N + col) = v1;
            } else {
#pragma unroll
                for (int u = 0; u < 2; u++) {
                    float v0 = acc[i][j][u * 2 + 0], v1 = acc[i][j][u * 2 + 1];
                    __nv_bfloat162 hh = __floats2bfloat162_rn(v0, v1);
                    float e0 = v0 - __bfloat162float(hh.x), e1 = v1 - __bfloat162float(hh.y);
                    size_t off = (size_t)(row0 + u * 8) * N + col;
                    *(uint32_t*)(Ch + off) = *(uint32_t*)&hh;
                    *(uint32_t*)(Cl + off) = pkbf(e0, e1);
                }
            }
        }
    }
}

// ---------------- K4: tensor-core flash attention (pre-split inputs) -------
struct FlashSmem {
    __nv_bfloat16 Kh[FQT][KSTR];
    __nv_bfloat16 Kl[FQT][KSTR];
    __nv_bfloat16 Vh[FCK][VSTR];
    __nv_bfloat16 Vl[FCK][VSTR];
};

__global__ __launch_bounds__(224) void flash_mma_kernel() {
    extern __shared__ __align__(16) char smraw[];
    FlashSmem& SM = *reinterpret_cast<FlashSmem*>(smraw);
    const int tid = threadIdx.x;
    const int warp = tid >> 5, lane = tid & 31;
    const int b = blockIdx.z, h = blockIdx.y, qb = blockIdx.x;
    const int q8 = lane >> 3, rr = lane & 7;
    const int gid = lane >> 2, tig = lane & 3;
    const float scale = 0.17677669529663687f;

    // ---- stage Q tile (112x32 bf16 hi/lo) ----
    {
        const __nv_bfloat16* Qh = g_qkvh + (size_t)(b * L_ + qb * FQT) * QKVN_ + h * EH_;
        const __nv_bfloat16* Ql = g_qkvl + (size_t)(b * L_ + qb * FQT) * QKVN_ + h * EH_;
#pragma unroll
        for (int it = 0; it < 2; it++) {
            int idx = tid + it * 224;
            if (idx < 448) {
                int row = idx >> 2, c8 = (idx & 3) << 3;
                *(uint4*)&SM.Kh[row][c8] = *(const uint4*)(Qh + (size_t)row * QKVN_ + c8);
                *(uint4*)&SM.Kl[row][c8] = *(const uint4*)(Ql + (size_t)row * QKVN_ + c8);
            }
        }
    }
    __syncthreads();
    uint32_t qhf[2][4], qlf[2][4];
#pragma unroll
    for (int s = 0; s < 2; s++) {
        int arow = warp * 16 + (q8 & 1) * 8 + rr;
        int acol = s * 16 + (q8 >> 1) * 8;
        ldsm4(qhf[s][0], qhf[s][1], qhf[s][2], qhf[s][3], smem_u32(&SM.Kh[arow][acol]));
        ldsm4(qlf[s][0], qlf[s][1], qlf[s][2], qlf[s][3], smem_u32(&SM.Kl[arow][acol]));
    }

    float out[16][4];
#pragma unroll
    for (int j = 0; j < 16; j++)
#pragma unroll
        for (int e = 0; e < 4; e++) out[j][e] = 0.f;
    float m0 = -1e30f, m1 = -1e30f, l0s = 0.f, l1s = 0.f;

    const int r0 = qb * FQT + warp * 16 + gid;
    const __nv_bfloat16* biasbase = g_biasbf + ((size_t)h * L_ + r0) * L_;

    for (int kc = 0; kc < 7; kc++) {
        int j0 = kc * FCK;
        __syncthreads();
        // ---- stage K chunk (112x32) hi/lo ----
        {
            const __nv_bfloat16* Kh = g_qkvh + (size_t)(b * L_ + j0) * QKVN_ + h * EH_ + QK_;
            const __nv_bfloat16* Kl = g_qkvl + (size_t)(b * L_ + j0) * QKVN_ + h * EH_ + QK_;
#pragma unroll
            for (int it = 0; it < 2; it++) {
                int idx = tid + it * 224;
                if (idx < 448) {
                    int row = idx >> 2, c8 = (idx & 3) << 3;
                    *(uint4*)&SM.Kh[row][c8] = *(const uint4*)(Kh + (size_t)row * QKVN_ + c8);
                    *(uint4*)&SM.Kl[row][c8] = *(const uint4*)(Kl + (size_t)row * QKVN_ + c8);
                }
            }
        }
        // ---- stage V chunk (112x128) hi/lo ----
        {
            const __nv_bfloat16* Vh = g_qkvh + (size_t)(b * L_ + j0) * QKVN_ + h * EH_ + 2 * QK_;
            const __nv_bfloat16* Vl = g_qkvl + (size_t)(b * L_ + j0) * QKVN_ + h * EH_ + 2 * QK_;
#pragma unroll
            for (int it = 0; it < 8; it++) {
                int idx = tid + it * 224;
                int row = idx >> 4, c8 = (idx & 15) << 3;
                *(uint4*)&SM.Vh[row][c8] = *(const uint4*)(Vh + (size_t)row * QKVN_ + c8);
                *(uint4*)&SM.Vl[row][c8] = *(const uint4*)(Vl + (size_t)row * QKVN_ + c8);
            }
        }
        __syncthreads();

        // ---- S = Q K^T (3-term split) ----
        float sa[14][4];
#pragma unroll
        for (int t = 0; t < 14; t++)
#pragma unroll
            for (int e = 0; e < 4; e++) sa[t][e] = 0.f;
#pragma unroll
        for (int s = 0; s < 2; s++) {
#pragma unroll
            for (int t = 0; t < 14; t++) {
                uint32_t bh[2], bl[2];
                int brow = t * 8 + rr;
                int bcol = s * 16 + (q8 & 1) * 8;
                ldsm2(bh[0], bh[1], smem_u32(&SM.Kh[brow][bcol]));
                ldsm2(bl[0], bl[1], smem_u32(&SM.Kl[brow][bcol]));
                mma16816(sa[t], qhf[s], bh);
                mma16816(sa[t], qhf[s], bl);
                mma16816(sa[t], qlf[s], bh);
            }
        }

        // ---- bias + scale + row max ----
        float ml0 = -1e30f, ml1 = -1e30f;
#pragma unroll
        for (int t = 0; t < 14; t++) {
            int col = j0 + t * 8 + tig * 2;
            float2 b0 = __bfloat1622float2(*(const __nv_bfloat162*)(biasbase + col));
            float2 b1 = __bfloat1622float2(*(const __nv_bfloat162*)(biasbase + (size_t)8 * L_ + col));
            sa[t][0] = fmaf(sa[t][0], scale, b0.x);
            sa[t][1] = fmaf(sa[t][1], scale, b0.y);
            sa[t][2] = fmaf(sa[t][2], scale, b1.x);
            sa[t][3] = fmaf(sa[t][3], scale, b1.y);
            ml0 = fmaxf(ml0, fmaxf(sa[t][0], sa[t][1]));
            ml1 = fmaxf(ml1, fmaxf(sa[t][2], sa[t][3]));
        }
        ml0 = fmaxf(ml0, __shfl_xor_sync(0xffffffffu, ml0, 1));
        ml0 = fmaxf(ml0, __shfl_xor_sync(0xffffffffu, ml0, 2));
        ml1 = fmaxf(ml1, __shfl_xor_sync(0xffffffffu, ml1, 1));
        ml1 = fmaxf(ml1, __shfl_xor_sync(0xffffffffu, ml1, 2));
        float mn0 = fmaxf(m0, ml0), mn1 = fmaxf(m1, ml1);
        float c0 = __expf(m0 - mn0), c1 = __expf(m1 - mn1);
        m0 = mn0; m1 = mn1;
#pragma unroll
        for (int j = 0; j < 16; j++) {
            out[j][0] *= c0; out[j][1] *= c0;
            out[j][2] *= c1; out[j][3] *= c1;
        }

        // ---- exp -> P frags (hi/lo), row sums ----
        float rs0 = 0.f, rs1 = 0.f;
        uint32_t pah[7][4], pal[7][4];
#pragma unroll
        for (int s2 = 0; s2 < 7; s2++) {
#pragma unroll
            for (int u = 0; u < 2; u++) {
                int t = s2 * 2 + u;
                float p0 = __expf(sa[t][0] - mn0);
                float p1 = __expf(sa[t][1] - mn0);
                float p2 = __expf(sa[t][2] - mn1);
                float p3 = __expf(sa[t][3] - mn1);
                rs0 += p0 + p1; rs1 += p2 + p3;
                __nv_bfloat162 h01 = __floats2bfloat162_rn(p0, p1);
                __nv_bfloat162 h23 = __floats2bfloat162_rn(p2, p3);
                float e0 = p0 - __bfloat162float(h01.x), e1 = p1 - __bfloat162float(h01.y);
                float e2 = p2 - __bfloat162float(h23.x), e3 = p3 - __bfloat162float(h23.y);
                pah[s2][u * 2 + 0] = *(uint32_t*)&h01;
                pah[s2][u * 2 + 1] = *(uint32_t*)&h23;
                pal[s2][u * 2 + 0] = pkbf(e0, e1);
                pal[s2][u * 2 + 1] = pkbf(e2, e3);
            }
        }
        rs0 += __shfl_xor_sync(0xffffffffu, rs0, 1);
        rs0 += __shfl_xor_sync(0xffffffffu, rs0, 2);
        rs1 += __shfl_xor_sync(0xffffffffu, rs1, 1);
        rs1 += __shfl_xor_sync(0xffffffffu, rs1, 2);
        l0s = l0s * c0 + rs0;
        l1s = l1s * c1 + rs1;

        // ---- out += P V (3-term split) ----
#pragma unroll
        for (int j = 0; j < 16; j++) {
#pragma unroll
            for (int s2 = 0; s2 < 7; s2++) {
                uint32_t bvh[2], bvl[2];
                ldsm2t(bvh[0], bvh[1], smem_u32(&SM.Vh[s2 * 16 + (lane & 15)][j * 8]));
                ldsm2t(bvl[0], bvl[1], smem_u32(&SM.Vl[s2 * 16 + (lane & 15)][j * 8]));
                mma16816(out[j], pah[s2], bvh);
                mma16816(out[j], pah[s2], bvl);
                mma16816(out[j], pal[s2], bvh);
            }
        }
    }

    // ---- epilogue: normalize + split write for proj GEMM ----
    float inv0 = 1.0f / l0s, inv1 = 1.0f / l1s;
    __nv_bfloat16* oh = g_aoh + (size_t)(b * L_ + r0) * AON + h * VD_;
    __nv_bfloat16* ol = g_aol + (size_t)(b * L_ + r0) * AON + h * VD_;
#pragma unroll
    for (int j = 0; j < 16; j++) {
        int col = j * 8 + tig * 2;
        {
            float v0 = out[j][0] * inv0, v1 = out[j][1] * inv0;
            __nv_bfloat162 hh = __floats2bfloat162_rn(v0, v1);
            float e0 = v0 - __bfloat162float(hh.x), e1 = v1 - __bfloat162float(hh.y);
            *(uint32_t*)(oh + col) = *(uint32_t*)&hh;
            *(uint32_t*)(ol + col) = pkbf(e0, e1);
        }
        {
            float v0 = out[j][2] * inv1, v1 = out[j][3] * inv1;
            __nv_bfloat162 hh = __floats2bfloat162_rn(v0, v1);
            float e0 = v0 - __bfloat162float(hh.x), e1 = v1 - __bfloat162float(hh.y);
            *(uint32_t*)(oh + (size_t)8 * AON + col) = *(uint32_t*)&hh;
            *(uint32_t*)(ol + (size_t)8 * AON + col) = pkbf(e0, e1);
        }
    }
}

// ---------------- launch ---------------------------------------------------
extern "C" void kernel_launch(void* const* d_in, const int* in_sizes, int n_in,
                              void* d_out, int out_size) {
    const float* x         = (const float*)d_in[0];   // (16,784,384)
    const float* Wqkv      = (const float*)d_in[1];   // (1536,384)
    const float* Wproj     = (const float*)d_in[2];   // (384,1024)
    const float* bproj     = (const float*)d_in[3];   // (384,)
    const float* ab_table  = (const float*)d_in[4];   // (8,625)
    const int*   bias_idxs = (const int*)d_in[5];     // (625,625)
    float* out = (float*)d_out;

    __nv_bfloat16 *pxh, *pxl, *pwqh, *pwql, *pwph, *pwpl, *pqkvh, *pqkvl, *paoh, *paol;
    cudaGetSymbolAddress((void**)&pxh, g_xh);   cudaGetSymbolAddress((void**)&pxl, g_xl);
    cudaGetSymbolAddress((void**)&pwqh, g_wqh); cudaGetSymbolAddress((void**)&pwql, g_wql);
    cudaGetSymbolAddress((void**)&pwph, g_wph); cudaGetSymbolAddress((void**)&pwpl, g_wpl);
    cudaGetSymbolAddress((void**)&pqkvh, g_qkvh); cudaGetSymbolAddress((void**)&pqkvl, g_qkvl);
    cudaGetSymbolAddress((void**)&paoh, g_aoh);   cudaGetSymbolAddress((void**)&paol, g_aol);

    const int FSM = (int)sizeof(FlashSmem);
    cudaFuncSetAttribute(flash_mma_kernel, cudaFuncAttributeMaxDynamicSharedMemorySize, FSM);

    build_interp_kernel<<<1, 1024>>>();

    const int totAb = H_ * RESI_ * RESI_;
    gather_ab_kernel<<<(totAb + 255) / 256, 256>>>(ab_table, bias_idxs);

    build_bias_kernel<<<(H_ * L_ * L_) / 256, 256>>>();

    // one-shot splits
    {
        int n4 = (B_ * L_ * D_) / 4;
        split_kernel<<<(n4 + 255) / 256, 256>>>(x, pxh, pxl, n4);
        n4 = (QKVN_ * D_) / 4;
        split_kernel<<<(n4 + 255) / 256, 256>>>(Wqkv, pwqh, pwql, n4);
        n4 = (D_ * AON) / 4;
        split_kernel<<<(n4 + 255) / 256, 256>>>(Wproj, pwph, pwpl, n4);
    }

    dim3 gqkv(QKVN_ / 128, (B_ * L_) / 128);
    mma_gemm_nt<0><<<gqkv, 256>>>(pxh, pxl, pwqh, pwql, nullptr,
                                  pqkvh, pqkvl, nullptr, B_ * L_, QKVN_, D_);

    dim3 gatt(L_ / FQT, H_, B_);
    flash_mma_kernel<<<gatt, 224, FSM>>>();

    dim3 gproj(D_ / 128, (B_ * L_) / 128);
    mma_gemm_nt<1><<<gproj, 256>>>(paoh, paol, pwph, pwpl, bproj,
                                   nullptr, nullptr, out, B_ * L_, D_, AON);
}

// round 7
// speedup vs baseline: 1.1421x; 1.1421x over previous
#include <cuda_runtime.h>
#include <cuda_bf16.h>
#include <math.h>
#include <cstdint>

#define B_     16
#define L_     784
#define D_     384
#define H_     8
#define QK_    32
#define VD_    128
#define EH_    192          // per-head qkv width
#define QKVN_  1536
#define RESI_  625

#define FQT 112             // q rows per CTA (784 = 7*112)
#define FCK 112             // keys per chunk
#define VSTR 136            // V smem stride in bf16 (conflict-free trans ldsm)
#define KSTR 40             // K/Q smem stride in bf16
#define AON  (H_ * VD_)     // 1024
#define GS   40             // GEMM smem stride

// ---------------- scratch (static device globals; no runtime alloc) --------
__device__ __nv_bfloat16 g_qkvh[(size_t)B_ * L_ * QKVN_];
__device__ __nv_bfloat16 g_qkvl[(size_t)B_ * L_ * QKVN_];
__device__ __nv_bfloat16 g_aoh[(size_t)B_ * L_ * AON];
__device__ __nv_bfloat16 g_aol[(size_t)B_ * L_ * AON];
__device__ __nv_bfloat16 g_biasbf[(size_t)H_ * L_ * L_];
__device__ float g_abg[(size_t)H_ * RESI_ * RESI_];
__device__ float g_tmp[(size_t)H_ * L_ * RESI_];
__device__ __nv_bfloat16 g_xh[(size_t)B_ * L_ * D_];
__device__ __nv_bfloat16 g_xl[(size_t)B_ * L_ * D_];
__device__ __nv_bfloat16 g_wqh[QKVN_ * D_];
__device__ __nv_bfloat16 g_wql[QKVN_ * D_];
__device__ __nv_bfloat16 g_wph[D_ * AON];
__device__ __nv_bfloat16 g_wpl[D_ * AON];
__device__ float g_iw[L_ * 4];
__device__ int   g_ii[L_ * 4];

__device__ __forceinline__ uint32_t smem_u32(const void* p) {
    uint32_t a;
    asm("{ .reg .u64 t; cvta.to.shared.u64 t, %1; cvt.u32.u64 %0, t; }" : "=r"(a) : "l"(p));
    return a;
}
__device__ __forceinline__ uint32_t pkbf(float a, float b) {
    __nv_bfloat162 t = __floats2bfloat162_rn(a, b);
    return *reinterpret_cast<uint32_t*>(&t);
}
__device__ __forceinline__ void cpa16(uint32_t s, const void* g) {
    asm volatile("cp.async.cg.shared.global [%0], [%1], 16;" :: "r"(s), "l"(g));
}
__device__ __forceinline__ void cpa_commit() {
    asm volatile("cp.async.commit_group;" ::: "memory");
}
template <int N> __device__ __forceinline__ void cpa_wait() {
    asm volatile("cp.async.wait_group %0;" :: "n"(N) : "memory");
}

// ---------------- K0: bicubic interp weights/indices -----------------------
__global__ void build_interp_kernel() {
    int o = blockIdx.x * blockDim.x + threadIdx.x;
    if (o >= L_) return;
    const float a = -0.75f;
    float scale = (float)RESI_ / (float)L_;
    float src = ((float)o + 0.5f) * scale - 0.5f;
    float f = floorf(src);
    float t = src - f;
    float xs[4] = { t + 1.0f, t, 1.0f - t, 2.0f - t };
#pragma unroll
    for (int i = 0; i < 4; i++) {
        float ax = fabsf(xs[i]);
        float w1 = ((a + 2.0f) * ax - (a + 3.0f)) * ax * ax + 1.0f;
        float w2 = a * (((ax - 5.0f) * ax + 8.0f) * ax - 4.0f);
        float w = (ax <= 1.0f) ? w1 : ((ax < 2.0f) ? w2 : 0.0f);
        g_iw[o * 4 + i] = w;
        int id = (int)f - 1 + i;
        id = id < 0 ? 0 : (id > RESI_ - 1 ? RESI_ - 1 : id);
        g_ii[o * 4 + i] = id;
    }
}

// ---------------- K1: ab gather --------------------------------------------
__global__ void gather_ab_kernel(const float* __restrict__ ab_table,
                                 const int* __restrict__ bias_idxs) {
    int i = blockIdx.x * blockDim.x + threadIdx.x;
    const int total = H_ * RESI_ * RESI_;
    if (i >= total) return;
    int h = i / (RESI_ * RESI_);
    int ij = i - h * (RESI_ * RESI_);
    g_abg[i] = ab_table[h * RESI_ + bias_idxs[ij]];
}

// ---------------- K2a/K2b: separable bias build ----------------------------
__global__ void bias_pass1_kernel() {
    int i = blockIdx.x * blockDim.x + threadIdx.x;
    const int total = H_ * L_ * RESI_;
    if (i >= total) return;
    int h = i / (L_ * RESI_);
    int r = i - h * (L_ * RESI_);
    int o = r / RESI_;
    int j = r - o * RESI_;
    const float* __restrict__ abh = g_abg + (size_t)h * RESI_ * RESI_;
    float s = 0.f;
#pragma unroll
    for (int a = 0; a < 4; a++)
        s = fmaf(g_iw[o * 4 + a], __ldg(abh + (size_t)g_ii[o * 4 + a] * RESI_ + j), s);
    g_tmp[i] = s;
}
__global__ void bias_pass2_kernel() {
    int i = blockIdx.x * blockDim.x + threadIdx.x;
    const int total = H_ * L_ * L_;
    if (i >= total) return;
    int h = i / (L_ * L_);
    int r = i - h * (L_ * L_);
    int o = r / L_;
    int p = r - o * L_;
    const float* __restrict__ tr = g_tmp + ((size_t)h * L_ + o) * RESI_;
    float s = 0.f;
#pragma unroll
    for (int bb = 0; bb < 4; bb++)
        s = fmaf(g_iw[p * 4 + bb], __ldg(tr + g_ii[p * 4 + bb]), s);
    g_biasbf[i] = __float2bfloat16(s);
}

// ---------------- split kernel: f32 -> bf16 hi + lo ------------------------
__global__ void split_kernel(const float* __restrict__ src,
                             __nv_bfloat16* __restrict__ dh,
                             __nv_bfloat16* __restrict__ dl, int n4) {
    int i = blockIdx.x * blockDim.x + threadIdx.x;
    if (i >= n4) return;
    float4 v = *(const float4*)(src + (size_t)i * 4);
    __nv_bfloat162 h01 = __floats2bfloat162_rn(v.x, v.y);
    __nv_bfloat162 h23 = __floats2bfloat162_rn(v.z, v.w);
    float l0 = v.x - __bfloat162float(h01.x), l1 = v.y - __bfloat162float(h01.y);
    float l2 = v.z - __bfloat162float(h23.x), l3 = v.w - __bfloat162float(h23.y);
    *(uint2*)(dh + (size_t)i * 4) = make_uint2(*(uint32_t*)&h01, *(uint32_t*)&h23);
    *(uint2*)(dl + (size_t)i * 4) = make_uint2(pkbf(l0, l1), pkbf(l2, l3));
}

// ---------------- mma.sync helpers -----------------------------------------
__device__ __forceinline__ void ldsm4(uint32_t& r0, uint32_t& r1, uint32_t& r2, uint32_t& r3,
                                      uint32_t addr) {
    asm volatile("ldmatrix.sync.aligned.m8n8.x4.shared.b16 {%0,%1,%2,%3}, [%4];"
                 : "=r"(r0), "=r"(r1), "=r"(r2), "=r"(r3) : "r"(addr));
}
__device__ __forceinline__ void ldsm4t(uint32_t& r0, uint32_t& r1, uint32_t& r2, uint32_t& r3,
                                       uint32_t addr) {
    asm volatile("ldmatrix.sync.aligned.m8n8.x4.trans.shared.b16 {%0,%1,%2,%3}, [%4];"
                 : "=r"(r0), "=r"(r1), "=r"(r2), "=r"(r3) : "r"(addr));
}
__device__ __forceinline__ void mma16816(float* d, const uint32_t* a, const uint32_t* b) {
    asm volatile("mma.sync.aligned.m16n8k16.row.col.f32.bf16.bf16.f32 "
                 "{%0,%1,%2,%3}, {%4,%5,%6,%7}, {%8,%9}, {%0,%1,%2,%3};"
                 : "+f"(d[0]), "+f"(d[1]), "+f"(d[2]), "+f"(d[3])
                 : "r"(a[0]), "r"(a[1]), "r"(a[2]), "r"(a[3]), "r"(b[0]), "r"(b[1]));
}

// ---------------- K3/K5: pipelined bf16-split GEMM --------------------------
// MODE 0: epilogue writes split bf16 (Ch, Cl).  MODE 1: writes f32 + bias.
template <int MODE>
__global__ __launch_bounds__(256) void mma_gemm_nt(
    const __nv_bfloat16* __restrict__ Ahg, const __nv_bfloat16* __restrict__ Alg,
    const __nv_bfloat16* __restrict__ Whg, const __nv_bfloat16* __restrict__ Wlg,
    const float* __restrict__ bias,
    __nv_bfloat16* __restrict__ Ch, __nv_bfloat16* __restrict__ Cl,
    float* __restrict__ Cf,
    int M, int N, int K)
{
    extern __shared__ __align__(16) __nv_bfloat16 smg[];
    const int TS = 128 * GS;          // elems per tile

    const int tid = threadIdx.x;
    const int wid = tid >> 5;
    const int lane = tid & 31;
    const int wm = wid >> 2;
    const int wn = wid & 3;
    const int bm = blockIdx.y * 128;
    const int bn = blockIdx.x * 128;
    const int q = lane >> 3;
    const int rr = lane & 7;

    float acc[4][4][4];
#pragma unroll
    for (int i = 0; i < 4; i++)
#pragma unroll
        for (int j = 0; j < 4; j++)
#pragma unroll
            for (int e = 0; e < 4; e++) acc[i][j][e] = 0.f;

    const int nch = K >> 5;

    auto prefetch = [&](int chunk, int stage) {
        int k0 = chunk << 5;
        __nv_bfloat16* T = smg + stage * 4 * TS;
        const __nv_bfloat16* gsrc[4] = {
            Ahg + (size_t)bm * K + k0, Alg + (size_t)bm * K + k0,
            Whg + (size_t)bn * K + k0, Wlg + (size_t)bn * K + k0 };
#pragma unroll
        for (int m = 0; m < 4; m++) {
            const __nv_bfloat16* gp = gsrc[m];
            __nv_bfloat16* tp = T + m * TS;
#pragma unroll
            for (int i = tid; i < 512; i += 256) {
                int row = i >> 2, seg = (i & 3) << 3;
                cpa16(smem_u32(tp + row * GS + seg), gp + (size_t)row * K + seg);
            }
        }
    };

    prefetch(0, 0); cpa_commit();
    prefetch(1, 1); cpa_commit();

    for (int i = 0; i < nch; i++) {
        if (i < nch - 1) cpa_wait<1>(); else cpa_wait<0>();
        __syncthreads();
        const __nv_bfloat16* T = smg + (i & 1) * 4 * TS;
        const __nv_bfloat16* TAh = T;
        const __nv_bfloat16* TAl = T + TS;
        const __nv_bfloat16* TBh = T + 2 * TS;
        const __nv_bfloat16* TBl = T + 3 * TS;

#pragma unroll
        for (int ks = 0; ks < 2; ks++) {
            int kc = ks * 16;
            uint32_t ah[4][4], al[4][4];
#pragma unroll
            for (int ii2 = 0; ii2 < 4; ii2++) {
                int arow = wm * 64 + ii2 * 16 + (q & 1) * 8 + rr;
                int acol = kc + (q >> 1) * 8;
                ldsm4(ah[ii2][0], ah[ii2][1], ah[ii2][2], ah[ii2][3],
                      smem_u32(TAh + arow * GS + acol));
                ldsm4(al[ii2][0], al[ii2][1], al[ii2][2], al[ii2][3],
                      smem_u32(TAl + arow * GS + acol));
            }
            uint32_t bh[4][2], bl[4][2];
#pragma unroll
            for (int jp = 0; jp < 2; jp++) {
                int brow = wn * 32 + (jp * 2 + (q >> 1)) * 8 + rr;
                int bcol = kc + (q & 1) * 8;
                ldsm4(bh[jp * 2][0], bh[jp * 2][1], bh[jp * 2 + 1][0], bh[jp * 2 + 1][1],
                      smem_u32(TBh + brow * GS + bcol));
                ldsm4(bl[jp * 2][0], bl[jp * 2][1], bl[jp * 2 + 1][0], bl[jp * 2 + 1][1],
                      smem_u32(TBl + brow * GS + bcol));
            }
#pragma unroll
            for (int ii2 = 0; ii2 < 4; ii2++)
#pragma unroll
                for (int j = 0; j < 4; j++) {
                    mma16816(acc[ii2][j], ah[ii2], bh[j]);
                    mma16816(acc[ii2][j], ah[ii2], bl[j]);
                    mma16816(acc[ii2][j], al[ii2], bh[j]);
                }
        }
        __syncthreads();
        if (i + 2 < nch) { prefetch(i + 2, i & 1); cpa_commit(); }
    }

    const int gid = lane >> 2;
    const int tig = lane & 3;
#pragma unroll
    for (int i = 0; i < 4; i++) {
#pragma unroll
        for (int j = 0; j < 4; j++) {
            int row0 = bm + wm * 64 + i * 16 + gid;
            int col = bn + wn * 32 + j * 8 + tig * 2;
            if (MODE == 1) {
                float2 v0 = make_float2(acc[i][j][0] + bias[col], acc[i][j][1] + bias[col + 1]);
                float2 v1 = make_float2(acc[i][j][2] + bias[col], acc[i][j][3] + bias[col + 1]);
                *(float2*)(Cf + (size_t)row0 * N + col) = v0;
                *(float2*)(Cf + (size_t)(row0 + 8) * N + col) = v1;
            } else {
#pragma unroll
                for (int u = 0; u < 2; u++) {
                    float v0 = acc[i][j][u * 2 + 0], v1 = acc[i][j][u * 2 + 1];
                    __nv_bfloat162 hh = __floats2bfloat162_rn(v0, v1);
                    float e0 = v0 - __bfloat162float(hh.x), e1 = v1 - __bfloat162float(hh.y);
                    size_t off = (size_t)(row0 + u * 8) * N + col;
                    *(uint32_t*)(Ch + off) = *(uint32_t*)&hh;
                    *(uint32_t*)(Cl + off) = pkbf(e0, e1);
                }
            }
        }
    }
}

// ---------------- K4: tensor-core flash attention, async double-buffered ---
struct FlashKV {
    __nv_bfloat16 Kh[FQT][KSTR];
    __nv_bfloat16 Kl[FQT][KSTR];
    __nv_bfloat16 Vh[FCK][VSTR];
    __nv_bfloat16 Vl[FCK][VSTR];
};
struct FlashSmemAll {
    __nv_bfloat16 Qh[FQT][KSTR];
    __nv_bfloat16 Ql[FQT][KSTR];
    FlashKV kv[2];
};

__global__ __launch_bounds__(224) void flash_mma_kernel() {
    extern __shared__ __align__(16) char smraw[];
    FlashSmemAll& SM = *reinterpret_cast<FlashSmemAll*>(smraw);
    const int tid = threadIdx.x;
    const int warp = tid >> 5, lane = tid & 31;
    const int b = blockIdx.z, h = blockIdx.y, qb = blockIdx.x;
    const int q8 = lane >> 3, rr = lane & 7;
    const int gid = lane >> 2, tig = lane & 3;
    const float scale = 0.17677669529663687f;

    auto pf_chunk = [&](int chunk, FlashKV* KV) {
        int j0 = chunk * FCK;
        const __nv_bfloat16* Khg = g_qkvh + (size_t)(b * L_ + j0) * QKVN_ + h * EH_ + QK_;
        const __nv_bfloat16* Klg = g_qkvl + (size_t)(b * L_ + j0) * QKVN_ + h * EH_ + QK_;
#pragma unroll
        for (int i = tid; i < 448; i += 224) {
            int row = i >> 2, seg = (i & 3) << 3;
            cpa16(smem_u32(&KV->Kh[row][seg]), Khg + (size_t)row * QKVN_ + seg);
            cpa16(smem_u32(&KV->Kl[row][seg]), Klg + (size_t)row * QKVN_ + seg);
        }
        const __nv_bfloat16* Vhg = Khg + QK_;
        const __nv_bfloat16* Vlg = Klg + QK_;
#pragma unroll
        for (int i = tid; i < 1792; i += 224) {
            int row = i >> 4, seg = (i & 15) << 3;
            cpa16(smem_u32(&KV->Vh[row][seg]), Vhg + (size_t)row * QKVN_ + seg);
            cpa16(smem_u32(&KV->Vl[row][seg]), Vlg + (size_t)row * QKVN_ + seg);
        }
    };

    // group0: Q tile + chunk0 ; group1: chunk1
    {
        const __nv_bfloat16* Qhg = g_qkvh + (size_t)(b * L_ + qb * FQT) * QKVN_ + h * EH_;
        const __nv_bfloat16* Qlg = g_qkvl + (size_t)(b * L_ + qb * FQT) * QKVN_ + h * EH_;
#pragma unroll
        for (int i = tid; i < 448; i += 224) {
            int row = i >> 2, seg = (i & 3) << 3;
            cpa16(smem_u32(&SM.Qh[row][seg]), Qhg + (size_t)row * QKVN_ + seg);
            cpa16(smem_u32(&SM.Ql[row][seg]), Qlg + (size_t)row * QKVN_ + seg);
        }
    }
    pf_chunk(0, &SM.kv[0]); cpa_commit();
    pf_chunk(1, &SM.kv[1]); cpa_commit();

    cpa_wait<1>();
    __syncthreads();

    uint32_t qhf[2][4], qlf[2][4];
#pragma unroll
    for (int s = 0; s < 2; s++) {
        int arow = warp * 16 + (q8 & 1) * 8 + rr;
        int acol = s * 16 + (q8 >> 1) * 8;
        ldsm4(qhf[s][0], qhf[s][1], qhf[s][2], qhf[s][3], smem_u32(&SM.Qh[arow][acol]));
        ldsm4(qlf[s][0], qlf[s][1], qlf[s][2], qlf[s][3], smem_u32(&SM.Ql[arow][acol]));
    }

    float out[16][4];
#pragma unroll
    for (int j = 0; j < 16; j++)
#pragma unroll
        for (int e = 0; e < 4; e++) out[j][e] = 0.f;
    float m0 = -1e30f, m1 = -1e30f, l0s = 0.f, l1s = 0.f;

    const int r0 = qb * FQT + warp * 16 + gid;
    const __nv_bfloat16* biasbase = g_biasbf + ((size_t)h * L_ + r0) * L_;

    for (int kc = 0; kc < 7; kc++) {
        int j0 = kc * FCK;
        if (kc > 0) {
            if (kc < 6) cpa_wait<1>(); else cpa_wait<0>();
            __syncthreads();
        }
        FlashKV& KV = SM.kv[kc & 1];

        // ---- S = Q K^T (3-term split), x4 frag loads ----
        float sa[14][4];
#pragma unroll
        for (int t = 0; t < 14; t++)
#pragma unroll
            for (int e = 0; e < 4; e++) sa[t][e] = 0.f;
#pragma unroll
        for (int s = 0; s < 2; s++) {
#pragma unroll
            for (int tp = 0; tp < 7; tp++) {
                uint32_t bh[4], bl[4];
                int brow = (tp * 2 + (q8 >> 1)) * 8 + rr;
                int bcol = s * 16 + (q8 & 1) * 8;
                ldsm4(bh[0], bh[1], bh[2], bh[3], smem_u32(&KV.Kh[brow][bcol]));
                ldsm4(bl[0], bl[1], bl[2], bl[3], smem_u32(&KV.Kl[brow][bcol]));
                mma16816(sa[tp * 2 + 0], qhf[s], bh + 0);
                mma16816(sa[tp * 2 + 0], qhf[s], bl + 0);
                mma16816(sa[tp * 2 + 0], qlf[s], bh + 0);
                mma16816(sa[tp * 2 + 1], qhf[s], bh + 2);
                mma16816(sa[tp * 2 + 1], qhf[s], bl + 2);
                mma16816(sa[tp * 2 + 1], qlf[s], bh + 2);
            }
        }

        // ---- bias + scale + row max ----
        float ml0 = -1e30f, ml1 = -1e30f;
#pragma unroll
        for (int t = 0; t < 14; t++) {
            int col = j0 + t * 8 + tig * 2;
            float2 b0 = __bfloat1622float2(*(const __nv_bfloat162*)(biasbase + col));
            float2 b1 = __bfloat1622float2(*(const __nv_bfloat162*)(biasbase + (size_t)8 * L_ + col));
            sa[t][0] = fmaf(sa[t][0], scale, b0.x);
            sa[t][1] = fmaf(sa[t][1], scale, b0.y);
            sa[t][2] = fmaf(sa[t][2], scale, b1.x);
            sa[t][3] = fmaf(sa[t][3], scale, b1.y);
            ml0 = fmaxf(ml0, fmaxf(sa[t][0], sa[t][1]));
            ml1 = fmaxf(ml1, fmaxf(sa[t][2], sa[t][3]));
        }
        ml0 = fmaxf(ml0, __shfl_xor_sync(0xffffffffu, ml0, 1));
        ml0 = fmaxf(ml0, __shfl_xor_sync(0xffffffffu, ml0, 2));
        ml1 = fmaxf(ml1, __shfl_xor_sync(0xffffffffu, ml1, 1));
        ml1 = fmaxf(ml1, __shfl_xor_sync(0xffffffffu, ml1, 2));
        float mn0 = fmaxf(m0, ml0), mn1 = fmaxf(m1, ml1);
        float c0 = __expf(m0 - mn0), c1 = __expf(m1 - mn1);
        m0 = mn0; m1 = mn1;
#pragma unroll
        for (int j = 0; j < 16; j++) {
            out[j][0] *= c0; out[j][1] *= c0;
            out[j][2] *= c1; out[j][3] *= c1;
        }

        // ---- exp -> P frags (hi/lo), row sums ----
        float rs0 = 0.f, rs1 = 0.f;
        uint32_t pah[7][4], pal[7][4];
#pragma unroll
        for (int s2 = 0; s2 < 7; s2++) {
#pragma unroll
            for (int u = 0; u < 2; u++) {
                int t = s2 * 2 + u;
                float p0 = __expf(sa[t][0] - mn0);
                float p1 = __expf(sa[t][1] - mn0);
                float p2 = __expf(sa[t][2] - mn1);
                float p3 = __expf(sa[t][3] - mn1);
                rs0 += p0 + p1; rs1 += p2 + p3;
                __nv_bfloat162 h01 = __floats2bfloat162_rn(p0, p1);
                __nv_bfloat162 h23 = __floats2bfloat162_rn(p2, p3);
                float e0 = p0 - __bfloat162float(h01.x), e1 = p1 - __bfloat162float(h01.y);
                float e2 = p2 - __bfloat162float(h23.x), e3 = p3 - __bfloat162float(h23.y);
                pah[s2][u * 2 + 0] = *(uint32_t*)&h01;
                pah[s2][u * 2 + 1] = *(uint32_t*)&h23;
                pal[s2][u * 2 + 0] = pkbf(e0, e1);
                pal[s2][u * 2 + 1] = pkbf(e2, e3);
            }
        }
        rs0 += __shfl_xor_sync(0xffffffffu, rs0, 1);
        rs0 += __shfl_xor_sync(0xffffffffu, rs0, 2);
        rs1 += __shfl_xor_sync(0xffffffffu, rs1, 1);
        rs1 += __shfl_xor_sync(0xffffffffu, rs1, 2);
        l0s = l0s * c0 + rs0;
        l1s = l1s * c1 + rs1;

        // ---- out += P V (3-term split), x4 trans frag loads ----
#pragma unroll
        for (int s2 = 0; s2 < 7; s2++) {
#pragma unroll
            for (int jp = 0; jp < 8; jp++) {
                uint32_t vh[4], vl[4];
                int vrow = s2 * 16 + (lane & 15);
                int vcol = (jp * 2 + (lane >> 4)) * 8;
                ldsm4t(vh[0], vh[1], vh[2], vh[3], smem_u32(&KV.Vh[vrow][vcol]));
                ldsm4t(vl[0], vl[1], vl[2], vl[3], smem_u32(&KV.Vl[vrow][vcol]));
                mma16816(out[jp * 2 + 0], pah[s2], vh + 0);
                mma16816(out[jp * 2 + 0], pah[s2], vl + 0);
                mma16816(out[jp * 2 + 0], pal[s2], vh + 0);
                mma16816(out[jp * 2 + 1], pah[s2], vh + 2);
                mma16816(out[jp * 2 + 1], pah[s2], vl + 2);
                mma16816(out[jp * 2 + 1], pal[s2], vh + 2);
            }
        }
        __syncthreads();
        if (kc + 2 <= 6) { pf_chunk(kc + 2, &SM.kv[kc & 1]); cpa_commit(); }
    }

    // ---- epilogue: normalize + split write for proj GEMM ----
    float inv0 = 1.0f / l0s, inv1 = 1.0f / l1s;
    __nv_bfloat16* oh = g_aoh + (size_t)(b * L_ + r0) * AON + h * VD_;
    __nv_bfloat16* ol = g_aol + (size_t)(b * L_ + r0) * AON + h * VD_;
#pragma unroll
    for (int j = 0; j < 16; j++) {
        int col = j * 8 + tig * 2;
        {
            float v0 = out[j][0] * inv0, v1 = out[j][1] * inv0;
            __nv_bfloat162 hh = __floats2bfloat162_rn(v0, v1);
            float e0 = v0 - __bfloat162float(hh.x), e1 = v1 - __bfloat162float(hh.y);
            *(uint32_t*)(oh + col) = *(uint32_t*)&hh;
            *(uint32_t*)(ol + col) = pkbf(e0, e1);
        }
        {
            float v0 = out[j][2] * inv1, v1 = out[j][3] * inv1;
            __nv_bfloat162 hh = __floats2bfloat162_rn(v0, v1);
            float e0 = v0 - __bfloat162float(hh.x), e1 = v1 - __bfloat162float(hh.y);
            *(uint32_t*)(oh + (size_t)8 * AON + col) = *(uint32_t*)&hh;
            *(uint32_t*)(ol + (size_t)8 * AON + col) = pkbf(e0, e1);
        }
    }
}

// ---------------- launch ---------------------------------------------------
extern "C" void kernel_launch(void* const* d_in, const int* in_sizes, int n_in,
                              void* d_out, int out_size) {
    const float* x         = (const float*)d_in[0];
    const float* Wqkv      = (const float*)d_in[1];
    const float* Wproj     = (const float*)d_in[2];
    const float* bproj     = (const float*)d_in[3];
    const float* ab_table  = (const float*)d_in[4];
    const int*   bias_idxs = (const int*)d_in[5];
    float* out = (float*)d_out;

    __nv_bfloat16 *pxh, *pxl, *pwqh, *pwql, *pwph, *pwpl, *pqkvh, *pqkvl, *paoh, *paol;
    cudaGetSymbolAddress((void**)&pxh, g_xh);   cudaGetSymbolAddress((void**)&pxl, g_xl);
    cudaGetSymbolAddress((void**)&pwqh, g_wqh); cudaGetSymbolAddress((void**)&pwql, g_wql);
    cudaGetSymbolAddress((void**)&pwph, g_wph); cudaGetSymbolAddress((void**)&pwpl, g_wpl);
    cudaGetSymbolAddress((void**)&pqkvh, g_qkvh); cudaGetSymbolAddress((void**)&pqkvl, g_qkvl);
    cudaGetSymbolAddress((void**)&paoh, g_aoh);   cudaGetSymbolAddress((void**)&paol, g_aol);

    const int FSM = (int)sizeof(FlashSmemAll);                  // 175616
    cudaFuncSetAttribute(flash_mma_kernel, cudaFuncAttributeMaxDynamicSharedMemorySize, FSM);
    const int GSM = 2 * 4 * 128 * GS * (int)sizeof(__nv_bfloat16);   // 81920
    cudaFuncSetAttribute(mma_gemm_nt<0>, cudaFuncAttributeMaxDynamicSharedMemorySize, GSM);
    cudaFuncSetAttribute(mma_gemm_nt<1>, cudaFuncAttributeMaxDynamicSharedMemorySize, GSM);

    build_interp_kernel<<<1, 1024>>>();

    const int totAb = H_ * RESI_ * RESI_;
    gather_ab_kernel<<<(totAb + 255) / 256, 256>>>(ab_table, bias_idxs);

    const int totP1 = H_ * L_ * RESI_;
    bias_pass1_kernel<<<(totP1 + 255) / 256, 256>>>();
    const int totP2 = H_ * L_ * L_;
    bias_pass2_kernel<<<(totP2 + 255) / 256, 256>>>();

    {
        int n4 = (B_ * L_ * D_) / 4;
        split_kernel<<<(n4 + 255) / 256, 256>>>(x, pxh, pxl, n4);
        n4 = (QKVN_ * D_) / 4;
        split_kernel<<<(n4 + 255) / 256, 256>>>(Wqkv, pwqh, pwql, n4);
        n4 = (D_ * AON) / 4;
        split_kernel<<<(n4 + 255) / 256, 256>>>(Wproj, pwph, pwpl, n4);
    }

    dim3 gqkv(QKVN_ / 128, (B_ * L_) / 128);
    mma_gemm_nt<0><<<gqkv, 256, GSM>>>(pxh, pxl, pwqh, pwql, nullptr,
                                       pqkvh, pqkvl, nullptr, B_ * L_, QKVN_, D_);

    dim3 gatt(L_ / FQT, H_, B_);
    flash_mma_kernel<<<gatt, 224, FSM>>>();

    dim3 gproj(D_ / 128, (B_ * L_) / 128);
    mma_gemm_nt<1><<<gproj, 256, GSM>>>(paoh, paol, pwph, pwpl, bproj,
                                        nullptr, nullptr, out, B_ * L_, D_, AON);
}